// round 6
// baseline (speedup 1.0000x reference)
#include <cuda_runtime.h>
#include <cuda_bf16.h>

// ---------------------------------------------------------------------------
// GCNClassifier: 2x GCNConv (symmetric-normalized, weighted, self-loops) + ReLU
//                + linear classifier.  N=100000, E=3200000, 128->96->48->3.
//
//  - Per-launch dst-CSR build (histogram + 2-level scan + position scatter):
//    both aggregations become atomic-free per-node gather-sums.
//    norm = dinv[src]*w*dinv[dst]; degree includes the +1 self-loop.
//  - Aggregation: warp (C=96) / half-warp (C=48) per node, 3 columns per lane,
//    neighbor loop unrolled x4 for MLP; self-loop term dinv[d]^2 * h[d];
//    fused bias + ReLU.  Layer-2 epilogue also fuses the 48->3 classifier
//    (per-lane partial logits + width-16 shfl reduction) -- no separate
//    classifier kernel, no a2 buffer.
//  - Dense GEMMs: shared-memory row-tile kernels (tiny vs. the gathers).
//  - Edge-index dtype (int64 vs int32) auto-detected into a device flag.
//  - All lanes participate in shuffles even for out-of-range nodes (no
//    early-return before __shfl_down_sync).
// ---------------------------------------------------------------------------

#define MAXN 100000
#define MAXE 3200000
#define INC1 128
#define C1   96
#define C2   48

__device__ float g_deg[MAXN];
__device__ float g_dinv[MAXN];
__device__ int   g_cnt[MAXN];
__device__ int   g_rowstart[MAXN];
__device__ int   g_pos[MAXN];
__device__ int   g_csr_src[MAXE];
__device__ float g_csr_w[MAXE];
__device__ float g_h1[(size_t)MAXN * C1];
__device__ float g_a1[(size_t)MAXN * C1];
__device__ float g_h2[(size_t)MAXN * C2];
__device__ int   g_bsum[1024];
__device__ int   g_idx64;

// ---------------------------------------------------------------------------
// init degrees/counters; block 0 also detects edge-index dtype.
// (JAX without x64 demotes int64 -> int32; reading int32 pairs as int64
// yields values outside [0, n) with overwhelming probability.)
__global__ void k_init(const void* ei, int e, int n) {
    int i = blockIdx.x * blockDim.x + threadIdx.x;
    if (i < n) { g_deg[i] = 1.0f; g_cnt[i] = 0; }
    if (i == 0) g_idx64 = 1;
}

__global__ void k_detect(const void* ei, int e, int n) {
    int i = threadIdx.x;
    if (i < 256 && i < e) {
        const long long* p = (const long long*)ei;
        long long v = p[i];
        if (v < 0 || v >= (long long)n) atomicExch(&g_idx64, 0);
    }
}

__device__ __forceinline__ void load_edge(const void* ei, int i, int e,
                                          int is64, int& s, int& d) {
    if (is64) {
        const long long* p = (const long long*)ei;
        s = (int)p[i]; d = (int)p[e + i];
    } else {
        const int* p = (const int*)ei;
        s = p[i]; d = p[e + i];
    }
}

// Pass 1 over edges: weighted degree at dst + neighbor count at dst.
__global__ void k_edge1(const void* ei, const float* __restrict__ ew, int e) {
    int i = blockIdx.x * blockDim.x + threadIdx.x;
    if (i >= e) return;
    int is64 = g_idx64;
    int s, d; load_edge(ei, i, e, is64, s, d);
    (void)s;
    atomicAdd(&g_deg[d], ew[i]);
    atomicAdd(&g_cnt[d], 1);
}

__global__ void k_dinv(int n) {
    int i = blockIdx.x * blockDim.x + threadIdx.x;
    if (i < n) {
        float dg = g_deg[i];
        g_dinv[i] = (dg > 0.0f) ? rsqrtf(dg) : 0.0f;
    }
}

// --------------------------- exclusive scan of g_cnt ------------------------

__global__ void k_scan1(int n) {
    __shared__ int sh[512];
    int i = blockIdx.x * 512 + threadIdx.x;
    int v = (i < n) ? g_cnt[i] : 0;
    sh[threadIdx.x] = v;
    __syncthreads();
    for (int off = 1; off < 512; off <<= 1) {
        int t = (threadIdx.x >= off) ? sh[threadIdx.x - off] : 0;
        __syncthreads();
        sh[threadIdx.x] += t;
        __syncthreads();
    }
    if (i < n) g_rowstart[i] = sh[threadIdx.x] - v;   // exclusive within block
    if (threadIdx.x == 511) g_bsum[blockIdx.x] = sh[511];
}

__global__ void k_scan2(int nb) {
    __shared__ int sh[1024];
    int v = (threadIdx.x < nb) ? g_bsum[threadIdx.x] : 0;
    sh[threadIdx.x] = v;
    __syncthreads();
    for (int off = 1; off < 1024; off <<= 1) {
        int t = (threadIdx.x >= off) ? sh[threadIdx.x - off] : 0;
        __syncthreads();
        sh[threadIdx.x] += t;
        __syncthreads();
    }
    if (threadIdx.x < nb) g_bsum[threadIdx.x] = sh[threadIdx.x] - v;  // exclusive
}

__global__ void k_scan3(int n) {
    int i = blockIdx.x * blockDim.x + threadIdx.x;
    if (i < n) {
        int rs = g_rowstart[i] + g_bsum[i >> 9];
        g_rowstart[i] = rs;
        g_pos[i] = rs;
    }
}

// Pass 2 over edges: scatter (src, coeff) into CSR slots.
__global__ void k_fill(const void* ei, const float* __restrict__ ew, int e) {
    int i = blockIdx.x * blockDim.x + threadIdx.x;
    if (i >= e) return;
    int is64 = g_idx64;
    int s, d; load_edge(ei, i, e, is64, s, d);
    int p = atomicAdd(&g_pos[d], 1);
    g_csr_src[p] = s;
    g_csr_w[p] = g_dinv[s] * ew[i] * g_dinv[d];
}

// ------------------------------- dense GEMM --------------------------------
// blockDim = OUTC threads; ROWS rows per block; x-tile staged in shared
// (rows contiguous -> flat float4 copy), W streamed per-k (L1-resident).
template <int INC, int OUTC, int ROWS>
__device__ __forceinline__ void gemm_body(const float* __restrict__ X,
                                          const float* __restrict__ W,
                                          float* __restrict__ Y, int n) {
    __shared__ float xs[ROWS * INC];
    int r0 = blockIdx.x * ROWS;
    if (r0 >= n) return;
    int nr = n - r0; if (nr > ROWS) nr = ROWS;

    const float4* xsrc = (const float4*)(X + (size_t)r0 * INC);
    float4* xdst = (float4*)xs;
    int total = nr * INC / 4;
    for (int t = threadIdx.x; t < total; t += blockDim.x) xdst[t] = xsrc[t];
    __syncthreads();

    int col = threadIdx.x;
    float acc[ROWS];
#pragma unroll
    for (int r = 0; r < ROWS; r++) acc[r] = 0.0f;

    for (int k = 0; k < INC; k++) {
        float w = W[k * OUTC + col];
#pragma unroll
        for (int r = 0; r < ROWS; r++)
            acc[r] = fmaf(xs[r * INC + k], w, acc[r]);
    }
#pragma unroll
    for (int r = 0; r < ROWS; r++)
        if (r < nr) Y[(size_t)(r0 + r) * OUTC + col] = acc[r];
}

__global__ void k_gemm1(const float* __restrict__ X, const float* __restrict__ W,
                        int n) {
    gemm_body<INC1, C1, 16>(X, W, g_h1, n);
}
__global__ void k_gemm2(const float* __restrict__ W, int n) {
    gemm_body<C1, C2, 16>(g_a1, W, g_h2, n);
}

// --------------------------- layer-1 aggregation ---------------------------
// 32 lanes per node, 3 columns per lane (C1 = 96).  Atomic-free gather-sum
// over CSR neighbors (+ self-loop), unrolled x4 for MLP, fused bias + ReLU.
__global__ void k_agg1(const float* __restrict__ bias, int n) {
    const int LANES = 32;
    int sub  = threadIdx.x / LANES;
    int lane = threadIdx.x % LANES;
    int d = blockIdx.x * (blockDim.x / LANES) + sub;
    bool valid = (d < n);
    int dc = valid ? d : 0;

    const float* H = g_h1;
    float sd = g_dinv[dc];
    float ws = sd * sd;                       // self-loop: dinv[d]*1*dinv[d]
    const float* hd = H + (size_t)dc * C1;
    float a0 = ws * hd[lane];
    float a1 = ws * hd[lane + LANES];
    float a2 = ws * hd[lane + 2 * LANES];

    int e   = g_rowstart[dc];
    int end = valid ? (e + g_cnt[dc]) : e;

    for (; e + 3 < end; e += 4) {
        int   s0 = g_csr_src[e],     s1 = g_csr_src[e + 1];
        int   s2 = g_csr_src[e + 2], s3 = g_csr_src[e + 3];
        float w0 = g_csr_w[e],       w1 = g_csr_w[e + 1];
        float w2 = g_csr_w[e + 2],   w3 = g_csr_w[e + 3];
        const float* h0 = H + (size_t)s0 * C1;
        const float* h1 = H + (size_t)s1 * C1;
        const float* h2 = H + (size_t)s2 * C1;
        const float* h3 = H + (size_t)s3 * C1;
        // 12 independent gathers in flight before any consumption (MLP)
        float x00 = h0[lane], x01 = h0[lane + LANES], x02 = h0[lane + 2 * LANES];
        float x10 = h1[lane], x11 = h1[lane + LANES], x12 = h1[lane + 2 * LANES];
        float x20 = h2[lane], x21 = h2[lane + LANES], x22 = h2[lane + 2 * LANES];
        float x30 = h3[lane], x31 = h3[lane + LANES], x32 = h3[lane + 2 * LANES];
        a0 = fmaf(w0, x00, a0); a1 = fmaf(w0, x01, a1); a2 = fmaf(w0, x02, a2);
        a0 = fmaf(w1, x10, a0); a1 = fmaf(w1, x11, a1); a2 = fmaf(w1, x12, a2);
        a0 = fmaf(w2, x20, a0); a1 = fmaf(w2, x21, a1); a2 = fmaf(w2, x22, a2);
        a0 = fmaf(w3, x30, a0); a1 = fmaf(w3, x31, a1); a2 = fmaf(w3, x32, a2);
    }
    for (; e < end; e++) {
        int   s0 = g_csr_src[e];
        float w0 = g_csr_w[e];
        const float* h0 = H + (size_t)s0 * C1;
        a0 = fmaf(w0, h0[lane], a0);
        a1 = fmaf(w0, h0[lane + LANES], a1);
        a2 = fmaf(w0, h0[lane + 2 * LANES], a2);
    }

    if (valid) {
        float* o = g_a1 + (size_t)d * C1;
        o[lane]             = fmaxf(a0 + bias[lane], 0.0f);
        o[lane + LANES]     = fmaxf(a1 + bias[lane + LANES], 0.0f);
        o[lane + 2 * LANES] = fmaxf(a2 + bias[lane + 2 * LANES], 0.0f);
    }
}

// ----------------- layer-2 aggregation + fused classifier ------------------
// 16 lanes per node (C2 = 48).  After bias+ReLU, each lane computes partial
// logits against its 3 rows of Wc (9 L1-resident loads), then a width-16
// shfl reduction; lane 0 adds bc and writes the 3 logits.  All lanes stay
// converged through the shuffles (no early return).
__global__ void k_agg2_cls(const float* __restrict__ bias,
                           const float* __restrict__ Wc,
                           const float* __restrict__ bc,
                           float* __restrict__ out, int n) {
    const int LANES = 16;
    int sub  = threadIdx.x / LANES;
    int lane = threadIdx.x % LANES;
    int d = blockIdx.x * (blockDim.x / LANES) + sub;
    bool valid = (d < n);
    int dc = valid ? d : 0;

    const float* H = g_h2;
    float sd = g_dinv[dc];
    float ws = sd * sd;
    const float* hd = H + (size_t)dc * C2;
    float a0 = ws * hd[lane];
    float a1 = ws * hd[lane + LANES];
    float a2 = ws * hd[lane + 2 * LANES];

    int e   = g_rowstart[dc];
    int end = valid ? (e + g_cnt[dc]) : e;

    for (; e + 3 < end; e += 4) {
        int   s0 = g_csr_src[e],     s1 = g_csr_src[e + 1];
        int   s2 = g_csr_src[e + 2], s3 = g_csr_src[e + 3];
        float w0 = g_csr_w[e],       w1 = g_csr_w[e + 1];
        float w2 = g_csr_w[e + 2],   w3 = g_csr_w[e + 3];
        const float* h0 = H + (size_t)s0 * C2;
        const float* h1 = H + (size_t)s1 * C2;
        const float* h2 = H + (size_t)s2 * C2;
        const float* h3 = H + (size_t)s3 * C2;
        float x00 = h0[lane], x01 = h0[lane + LANES], x02 = h0[lane + 2 * LANES];
        float x10 = h1[lane], x11 = h1[lane + LANES], x12 = h1[lane + 2 * LANES];
        float x20 = h2[lane], x21 = h2[lane + LANES], x22 = h2[lane + 2 * LANES];
        float x30 = h3[lane], x31 = h3[lane + LANES], x32 = h3[lane + 2 * LANES];
        a0 = fmaf(w0, x00, a0); a1 = fmaf(w0, x01, a1); a2 = fmaf(w0, x02, a2);
        a0 = fmaf(w1, x10, a0); a1 = fmaf(w1, x11, a1); a2 = fmaf(w1, x12, a2);
        a0 = fmaf(w2, x20, a0); a1 = fmaf(w2, x21, a1); a2 = fmaf(w2, x22, a2);
        a0 = fmaf(w3, x30, a0); a1 = fmaf(w3, x31, a1); a2 = fmaf(w3, x32, a2);
    }
    for (; e < end; e++) {
        int   s0 = g_csr_src[e];
        float w0 = g_csr_w[e];
        const float* h0 = H + (size_t)s0 * C2;
        a0 = fmaf(w0, h0[lane], a0);
        a1 = fmaf(w0, h0[lane + LANES], a1);
        a2 = fmaf(w0, h0[lane + 2 * LANES], a2);
    }

    // bias + ReLU (hidden activations; k0 = lane, k1 = lane+16, k2 = lane+32)
    float v0 = fmaxf(a0 + bias[lane], 0.0f);
    float v1 = fmaxf(a1 + bias[lane + LANES], 0.0f);
    float v2 = fmaxf(a2 + bias[lane + 2 * LANES], 0.0f);

    // fused classifier: partial logits for this lane's 3 hidden dims
    const float* wr0 = Wc + lane * 3;                 // Wc[k0][0..2]
    const float* wr1 = Wc + (lane + LANES) * 3;       // Wc[k1][0..2]
    const float* wr2 = Wc + (lane + 2 * LANES) * 3;   // Wc[k2][0..2]
    float p0 = v0 * wr0[0] + v1 * wr1[0] + v2 * wr2[0];
    float p1 = v0 * wr0[1] + v1 * wr1[1] + v2 * wr2[1];
    float p2 = v0 * wr0[2] + v1 * wr1[2] + v2 * wr2[2];

#pragma unroll
    for (int off = 8; off >= 1; off >>= 1) {
        p0 += __shfl_down_sync(0xffffffffu, p0, off, LANES);
        p1 += __shfl_down_sync(0xffffffffu, p1, off, LANES);
        p2 += __shfl_down_sync(0xffffffffu, p2, off, LANES);
    }
    if (valid && lane == 0) {
        float* o = out + (size_t)d * 3;
        o[0] = p0 + bc[0];
        o[1] = p1 + bc[1];
        o[2] = p2 + bc[2];
    }
}

// ---------------------------------------------------------------------------

extern "C" void kernel_launch(void* const* d_in, const int* in_sizes, int n_in,
                              void* d_out, int out_size) {
    const float* x  = (const float*)d_in[0];
    const void*  ei = d_in[1];
    const float* ew = (const float*)d_in[2];
    const float* W1 = (const float*)d_in[3];
    const float* b1 = (const float*)d_in[4];
    const float* W2 = (const float*)d_in[5];
    const float* b2 = (const float*)d_in[6];
    const float* Wc = (const float*)d_in[7];
    const float* bc = (const float*)d_in[8];
    float* out = (float*)d_out;

    int n = in_sizes[0] / INC1;   // 100000
    int e = in_sizes[2];          // 3200000 (edge_weight count)

    int nbN  = (n + 255) / 256;
    int nbE  = (e + 255) / 256;
    int nbSc = (n + 511) / 512;

    // ---- graph preprocessing: degrees, dinv, dst-CSR ----
    k_init<<<nbN, 256>>>(ei, e, n);
    k_detect<<<1, 256>>>(ei, e, n);
    k_edge1<<<nbE, 256>>>(ei, ew, e);
    k_dinv<<<nbN, 256>>>(n);
    k_scan1<<<nbSc, 512>>>(n);
    k_scan2<<<1, 1024>>>(nbSc);
    k_scan3<<<nbN, 256>>>(n);
    k_fill<<<nbE, 256>>>(ei, ew, e);

    // ---- layer 1: x@W1 -> aggregate (+b1, ReLU) ----
    k_gemm1<<<(n + 15) / 16, C1>>>(x, W1, n);
    k_agg1<<<(n + 3) / 4, 128>>>(b1, n);

    // ---- layer 2: a1@W2 -> aggregate (+b2, ReLU) + fused classifier ----
    k_gemm2<<<(n + 15) / 16, C2>>>(W2, n);
    k_agg2_cls<<<(n + 7) / 8, 128>>>(b2, Wc, bc, out, n);
}

// round 7
// speedup vs baseline: 1.0858x; 1.0858x over previous
#include <cuda_runtime.h>
#include <cuda_bf16.h>

// ---------------------------------------------------------------------------
// GCNClassifier: 2x GCNConv (symmetric-normalized, weighted, self-loops) + ReLU
//                + linear classifier.  N=100000, E=3200000, 128->96->48->3.
//
//  R6 baseline (444.9us, passed) + this round:
//   - GEMMs rebuilt around packed fp32x2 FFMA2 (PTX fma.rn.f32x2): k-pair
//     accumulation, acc f32x2 = (even-k, odd-k) partials, W pre-packed into
//     float2 scratch.  Inner loop 17 issues / 2 k-steps / 8 rows vs 33/1/16
//     before (~1.9x).  Full-warp blocks (2*OUTC threads) fix gemm2's old
//     1.5-warp raggedness.
//   - k_dinv folded into k_scan1 (one fewer launch).
//  Unchanged: dst-CSR build (histogram + 2-level scan + position scatter ->
//  atomic-free aggregations), x4-unrolled MLP gather loops, fused bias+ReLU,
//  fused 48->3 classifier in the layer-2 epilogue, int64/int32 edge-index
//  auto-detect, shuffle-safe (no early return before __shfl).
// ---------------------------------------------------------------------------

#define MAXN 100000
#define MAXE 3200000
#define INC1 128
#define C1   96
#define C2   48

__device__ float g_deg[MAXN];
__device__ float g_dinv[MAXN];
__device__ int   g_cnt[MAXN];
__device__ int   g_rowstart[MAXN];
__device__ int   g_pos[MAXN];
__device__ int   g_csr_src[MAXE];
__device__ float g_csr_w[MAXE];
__device__ float g_h1[(size_t)MAXN * C1];
__device__ float g_a1[(size_t)MAXN * C1];
__device__ float g_h2[(size_t)MAXN * C2];
__device__ int   g_bsum[1024];
__device__ int   g_idx64;
__device__ float2 g_W1p[(INC1 / 2) * C1];   // (W1[2kp][c], W1[2kp+1][c])
__device__ float2 g_W2p[(C1 / 2) * C2];     // (W2[2kp][c], W2[2kp+1][c])

// ---------------------------- packed fp32x2 FMA ----------------------------
__device__ __forceinline__ unsigned long long ffma2(unsigned long long a,
                                                    unsigned long long b,
                                                    unsigned long long c) {
    unsigned long long d;
    asm("fma.rn.f32x2 %0, %1, %2, %3;" : "=l"(d) : "l"(a), "l"(b), "l"(c));
    return d;
}
__device__ __forceinline__ unsigned long long pack2(float lo, float hi) {
    unsigned long long r;
    asm("mov.b64 %0, {%1, %2};" : "=l"(r) : "f"(lo), "f"(hi));
    return r;
}
__device__ __forceinline__ float sum2(unsigned long long v) {
    float lo, hi;
    asm("mov.b64 {%0, %1}, %2;" : "=f"(lo), "=f"(hi) : "l"(v));
    return lo + hi;
}

// ---------------------------------------------------------------------------
__global__ void k_init(int n) {
    int i = blockIdx.x * blockDim.x + threadIdx.x;
    if (i < n) { g_deg[i] = 1.0f; g_cnt[i] = 0; }
    if (i == 0) g_idx64 = 1;
}

// Detect whether edge_index is int64 or int32 (JAX without x64 demotes to
// int32; reading int32 pairs as int64 lands outside [0, n) w.h.p.).
__global__ void k_detect(const void* ei, int e, int n) {
    int i = threadIdx.x;
    if (i < 256 && i < e) {
        const long long* p = (const long long*)ei;
        long long v = p[i];
        if (v < 0 || v >= (long long)n) atomicExch(&g_idx64, 0);
    }
}

__device__ __forceinline__ void load_edge(const void* ei, int i, int e,
                                          int is64, int& s, int& d) {
    if (is64) {
        const long long* p = (const long long*)ei;
        s = (int)p[i]; d = (int)p[e + i];
    } else {
        const int* p = (const int*)ei;
        s = p[i]; d = p[e + i];
    }
}

// Pass 1 over edges: weighted degree at dst + neighbor count at dst.
__global__ void k_edge1(const void* ei, const float* __restrict__ ew, int e) {
    int i = blockIdx.x * blockDim.x + threadIdx.x;
    if (i >= e) return;
    int is64 = g_idx64;
    int s, d; load_edge(ei, i, e, is64, s, d);
    (void)s;
    atomicAdd(&g_deg[d], ew[i]);
    atomicAdd(&g_cnt[d], 1);
}

// Pack W1/W2 k-pairs into float2 scratch for the FFMA2 GEMMs.
__global__ void k_packW(const float* __restrict__ W1,
                        const float* __restrict__ W2) {
    int i = blockIdx.x * blockDim.x + threadIdx.x;
    const int n1 = (INC1 / 2) * C1;     // 6144
    const int n2 = (C1 / 2) * C2;       // 2304
    if (i < n1) {
        int kp = i / C1, c = i % C1;
        g_W1p[i] = make_float2(W1[(2 * kp) * C1 + c], W1[(2 * kp + 1) * C1 + c]);
    } else if (i < n1 + n2) {
        int j = i - n1;
        int kp = j / C2, c = j % C2;
        g_W2p[j] = make_float2(W2[(2 * kp) * C2 + c], W2[(2 * kp + 1) * C2 + c]);
    }
}

// ----------------- exclusive scan of g_cnt (dinv fused in) ------------------
__global__ void k_scan1(int n) {
    __shared__ int sh[512];
    int i = blockIdx.x * 512 + threadIdx.x;
    if (i < n) {                              // fused k_dinv
        float dg = g_deg[i];
        g_dinv[i] = (dg > 0.0f) ? rsqrtf(dg) : 0.0f;
    }
    int v = (i < n) ? g_cnt[i] : 0;
    sh[threadIdx.x] = v;
    __syncthreads();
    for (int off = 1; off < 512; off <<= 1) {
        int t = (threadIdx.x >= off) ? sh[threadIdx.x - off] : 0;
        __syncthreads();
        sh[threadIdx.x] += t;
        __syncthreads();
    }
    if (i < n) g_rowstart[i] = sh[threadIdx.x] - v;   // exclusive within block
    if (threadIdx.x == 511) g_bsum[blockIdx.x] = sh[511];
}

__global__ void k_scan2(int nb) {
    __shared__ int sh[1024];
    int v = (threadIdx.x < nb) ? g_bsum[threadIdx.x] : 0;
    sh[threadIdx.x] = v;
    __syncthreads();
    for (int off = 1; off < 1024; off <<= 1) {
        int t = (threadIdx.x >= off) ? sh[threadIdx.x - off] : 0;
        __syncthreads();
        sh[threadIdx.x] += t;
        __syncthreads();
    }
    if (threadIdx.x < nb) g_bsum[threadIdx.x] = sh[threadIdx.x] - v;  // exclusive
}

__global__ void k_scan3(int n) {
    int i = blockIdx.x * blockDim.x + threadIdx.x;
    if (i < n) {
        int rs = g_rowstart[i] + g_bsum[i >> 9];
        g_rowstart[i] = rs;
        g_pos[i] = rs;
    }
}

// Pass 2 over edges: scatter (src, coeff) into CSR slots.
__global__ void k_fill(const void* ei, const float* __restrict__ ew, int e) {
    int i = blockIdx.x * blockDim.x + threadIdx.x;
    if (i >= e) return;
    int is64 = g_idx64;
    int s, d; load_edge(ei, i, e, is64, s, d);
    int p = atomicAdd(&g_pos[d], 1);
    g_csr_src[p] = s;
    g_csr_w[p] = g_dinv[s] * ew[i] * g_dinv[d];
}

// ---------------------------- FFMA2 dense GEMM -----------------------------
// block = 2*OUTC threads: col = t % OUTC, rowhalf = t / OUTC (8 rows each).
// acc[r] is f32x2 = (partial over even k, partial over odd k); per k-pair:
// 8 broadcast LDS.64 (xs) + 1 LDG.64 (packed W, L1/L2-resident) + 8 FFMA2.
template <int INC, int OUTC>
__device__ __forceinline__ void gemm_body(const float* __restrict__ X,
                                          const float2* __restrict__ Wp,
                                          float* __restrict__ Y, int n) {
    const int ROWS = 16;
    __shared__ __align__(16) float xs[ROWS * INC];
    int r0 = blockIdx.x * ROWS;
    if (r0 >= n) return;
    int nr = n - r0; if (nr > ROWS) nr = ROWS;

    const float4* xsrc = (const float4*)(X + (size_t)r0 * INC);
    float4* xdst = (float4*)xs;
    int total = nr * INC / 4;
    for (int t = threadIdx.x; t < total; t += blockDim.x) xdst[t] = xsrc[t];
    __syncthreads();

    int col = threadIdx.x % OUTC;
    int rh  = threadIdx.x / OUTC;           // 0 or 1
    const float* xbase = xs + (rh * 8) * INC;

    unsigned long long acc[8];
#pragma unroll
    for (int r = 0; r < 8; r++) acc[r] = pack2(0.0f, 0.0f);

#pragma unroll 8
    for (int kp = 0; kp < INC / 2; kp++) {
        float2 wv = Wp[kp * OUTC + col];
        unsigned long long w2 = pack2(wv.x, wv.y);
#pragma unroll
        for (int r = 0; r < 8; r++) {
            unsigned long long x2 =
                *(const unsigned long long*)(xbase + r * INC + 2 * kp);
            acc[r] = ffma2(x2, w2, acc[r]);
        }
    }

#pragma unroll
    for (int r = 0; r < 8; r++) {
        int row = rh * 8 + r;
        if (row < nr) Y[(size_t)(r0 + row) * OUTC + col] = sum2(acc[r]);
    }
}

__global__ void k_gemm1(const float* __restrict__ X, int n) {
    gemm_body<INC1, C1>(X, g_W1p, g_h1, n);
}
__global__ void k_gemm2(int n) {
    gemm_body<C1, C2>(g_a1, g_W2p, g_h2, n);
}

// --------------------------- layer-1 aggregation ---------------------------
// 32 lanes per node, 3 columns per lane (C1 = 96).  Atomic-free gather-sum
// over CSR neighbors (+ self-loop), unrolled x4 for MLP, fused bias + ReLU.
__global__ void k_agg1(const float* __restrict__ bias, int n) {
    const int LANES = 32;
    int sub  = threadIdx.x / LANES;
    int lane = threadIdx.x % LANES;
    int d = blockIdx.x * (blockDim.x / LANES) + sub;
    bool valid = (d < n);
    int dc = valid ? d : 0;

    const float* H = g_h1;
    float sd = g_dinv[dc];
    float ws = sd * sd;                       // self-loop: dinv[d]*1*dinv[d]
    const float* hd = H + (size_t)dc * C1;
    float a0 = ws * hd[lane];
    float a1 = ws * hd[lane + LANES];
    float a2 = ws * hd[lane + 2 * LANES];

    int e   = g_rowstart[dc];
    int end = valid ? (e + g_cnt[dc]) : e;

    for (; e + 3 < end; e += 4) {
        int   s0 = g_csr_src[e],     s1 = g_csr_src[e + 1];
        int   s2 = g_csr_src[e + 2], s3 = g_csr_src[e + 3];
        float w0 = g_csr_w[e],       w1 = g_csr_w[e + 1];
        float w2 = g_csr_w[e + 2],   w3 = g_csr_w[e + 3];
        const float* h0 = H + (size_t)s0 * C1;
        const float* h1 = H + (size_t)s1 * C1;
        const float* h2 = H + (size_t)s2 * C1;
        const float* h3 = H + (size_t)s3 * C1;
        // 12 independent gathers in flight before any consumption (MLP)
        float x00 = h0[lane], x01 = h0[lane + LANES], x02 = h0[lane + 2 * LANES];
        float x10 = h1[lane], x11 = h1[lane + LANES], x12 = h1[lane + 2 * LANES];
        float x20 = h2[lane], x21 = h2[lane + LANES], x22 = h2[lane + 2 * LANES];
        float x30 = h3[lane], x31 = h3[lane + LANES], x32 = h3[lane + 2 * LANES];
        a0 = fmaf(w0, x00, a0); a1 = fmaf(w0, x01, a1); a2 = fmaf(w0, x02, a2);
        a0 = fmaf(w1, x10, a0); a1 = fmaf(w1, x11, a1); a2 = fmaf(w1, x12, a2);
        a0 = fmaf(w2, x20, a0); a1 = fmaf(w2, x21, a1); a2 = fmaf(w2, x22, a2);
        a0 = fmaf(w3, x30, a0); a1 = fmaf(w3, x31, a1); a2 = fmaf(w3, x32, a2);
    }
    for (; e < end; e++) {
        int   s0 = g_csr_src[e];
        float w0 = g_csr_w[e];
        const float* h0 = H + (size_t)s0 * C1;
        a0 = fmaf(w0, h0[lane], a0);
        a1 = fmaf(w0, h0[lane + LANES], a1);
        a2 = fmaf(w0, h0[lane + 2 * LANES], a2);
    }

    if (valid) {
        float* o = g_a1 + (size_t)d * C1;
        o[lane]             = fmaxf(a0 + bias[lane], 0.0f);
        o[lane + LANES]     = fmaxf(a1 + bias[lane + LANES], 0.0f);
        o[lane + 2 * LANES] = fmaxf(a2 + bias[lane + 2 * LANES], 0.0f);
    }
}

// ----------------- layer-2 aggregation + fused classifier ------------------
// 16 lanes per node (C2 = 48).  After bias+ReLU, each lane computes partial
// logits against its 3 rows of Wc, then a width-16 shfl reduction; lane 0
// adds bc and writes.  All lanes stay converged through the shuffles.
__global__ void k_agg2_cls(const float* __restrict__ bias,
                           const float* __restrict__ Wc,
                           const float* __restrict__ bc,
                           float* __restrict__ out, int n) {
    const int LANES = 16;
    int sub  = threadIdx.x / LANES;
    int lane = threadIdx.x % LANES;
    int d = blockIdx.x * (blockDim.x / LANES) + sub;
    bool valid = (d < n);
    int dc = valid ? d : 0;

    const float* H = g_h2;
    float sd = g_dinv[dc];
    float ws = sd * sd;
    const float* hd = H + (size_t)dc * C2;
    float a0 = ws * hd[lane];
    float a1 = ws * hd[lane + LANES];
    float a2 = ws * hd[lane + 2 * LANES];

    int e   = g_rowstart[dc];
    int end = valid ? (e + g_cnt[dc]) : e;

    for (; e + 3 < end; e += 4) {
        int   s0 = g_csr_src[e],     s1 = g_csr_src[e + 1];
        int   s2 = g_csr_src[e + 2], s3 = g_csr_src[e + 3];
        float w0 = g_csr_w[e],       w1 = g_csr_w[e + 1];
        float w2 = g_csr_w[e + 2],   w3 = g_csr_w[e + 3];
        const float* h0 = H + (size_t)s0 * C2;
        const float* h1 = H + (size_t)s1 * C2;
        const float* h2 = H + (size_t)s2 * C2;
        const float* h3 = H + (size_t)s3 * C2;
        float x00 = h0[lane], x01 = h0[lane + LANES], x02 = h0[lane + 2 * LANES];
        float x10 = h1[lane], x11 = h1[lane + LANES], x12 = h1[lane + 2 * LANES];
        float x20 = h2[lane], x21 = h2[lane + LANES], x22 = h2[lane + 2 * LANES];
        float x30 = h3[lane], x31 = h3[lane + LANES], x32 = h3[lane + 2 * LANES];
        a0 = fmaf(w0, x00, a0); a1 = fmaf(w0, x01, a1); a2 = fmaf(w0, x02, a2);
        a0 = fmaf(w1, x10, a0); a1 = fmaf(w1, x11, a1); a2 = fmaf(w1, x12, a2);
        a0 = fmaf(w2, x20, a0); a1 = fmaf(w2, x21, a1); a2 = fmaf(w2, x22, a2);
        a0 = fmaf(w3, x30, a0); a1 = fmaf(w3, x31, a1); a2 = fmaf(w3, x32, a2);
    }
    for (; e < end; e++) {
        int   s0 = g_csr_src[e];
        float w0 = g_csr_w[e];
        const float* h0 = H + (size_t)s0 * C2;
        a0 = fmaf(w0, h0[lane], a0);
        a1 = fmaf(w0, h0[lane + LANES], a1);
        a2 = fmaf(w0, h0[lane + 2 * LANES], a2);
    }

    // bias + ReLU (hidden activations; k0 = lane, k1 = lane+16, k2 = lane+32)
    float v0 = fmaxf(a0 + bias[lane], 0.0f);
    float v1 = fmaxf(a1 + bias[lane + LANES], 0.0f);
    float v2 = fmaxf(a2 + bias[lane + 2 * LANES], 0.0f);

    // fused classifier: partial logits for this lane's 3 hidden dims
    const float* wr0 = Wc + lane * 3;                 // Wc[k0][0..2]
    const float* wr1 = Wc + (lane + LANES) * 3;       // Wc[k1][0..2]
    const float* wr2 = Wc + (lane + 2 * LANES) * 3;   // Wc[k2][0..2]
    float p0 = v0 * wr0[0] + v1 * wr1[0] + v2 * wr2[0];
    float p1 = v0 * wr0[1] + v1 * wr1[1] + v2 * wr2[1];
    float p2 = v0 * wr0[2] + v1 * wr1[2] + v2 * wr2[2];

#pragma unroll
    for (int off = 8; off >= 1; off >>= 1) {
        p0 += __shfl_down_sync(0xffffffffu, p0, off, LANES);
        p1 += __shfl_down_sync(0xffffffffu, p1, off, LANES);
        p2 += __shfl_down_sync(0xffffffffu, p2, off, LANES);
    }
    if (valid && lane == 0) {
        float* o = out + (size_t)d * 3;
        o[0] = p0 + bc[0];
        o[1] = p1 + bc[1];
        o[2] = p2 + bc[2];
    }
}

// ---------------------------------------------------------------------------

extern "C" void kernel_launch(void* const* d_in, const int* in_sizes, int n_in,
                              void* d_out, int out_size) {
    const float* x  = (const float*)d_in[0];
    const void*  ei = d_in[1];
    const float* ew = (const float*)d_in[2];
    const float* W1 = (const float*)d_in[3];
    const float* b1 = (const float*)d_in[4];
    const float* W2 = (const float*)d_in[5];
    const float* b2 = (const float*)d_in[6];
    const float* Wc = (const float*)d_in[7];
    const float* bc = (const float*)d_in[8];
    float* out = (float*)d_out;

    int n = in_sizes[0] / INC1;   // 100000
    int e = in_sizes[2];          // 3200000 (edge_weight count)

    int nbN  = (n + 255) / 256;
    int nbE  = (e + 255) / 256;
    int nbSc = (n + 511) / 512;
    int nbW  = ((INC1 / 2) * C1 + (C1 / 2) * C2 + 255) / 256;

    // ---- graph preprocessing: degrees, dst-CSR; W packing overlapped ----
    k_init<<<nbN, 256>>>(n);
    k_detect<<<1, 256>>>(ei, e, n);
    k_edge1<<<nbE, 256>>>(ei, ew, e);
    k_packW<<<nbW, 256>>>(W1, W2);
    k_scan1<<<nbSc, 512>>>(n);          // also computes dinv
    k_scan2<<<1, 1024>>>(nbSc);
    k_scan3<<<nbN, 256>>>(n);
    k_fill<<<nbE, 256>>>(ei, ew, e);

    // ---- layer 1: x@W1 -> aggregate (+b1, ReLU) ----
    k_gemm1<<<(n + 15) / 16, 2 * C1>>>(x, n);
    k_agg1<<<(n + 3) / 4, 128>>>(b1, n);

    // ---- layer 2: a1@W2 -> aggregate (+b2, ReLU) + fused classifier ----
    k_gemm2<<<(n + 15) / 16, 2 * C2>>>(n);
    k_agg2_cls<<<(n + 7) / 8, 128>>>(b2, Wc, bc, out, n);
}